// round 3
// baseline (speedup 1.0000x reference)
#include <cuda_runtime.h>
#include <cuda_bf16.h>
#include <cstdint>

// Problem constants (from reference)
#define NN    50000      // nodes
#define EE    800000     // edges
#define NODE_D 128
#define EDGE_D 16
#define HID   300

// ---------------- scratch (device globals; no allocs allowed) ----------------
__device__ float g_inc[NN * EDGE_D];        // 3.2 MB
__device__ float g_agg[(size_t)NN * HID];   // 60 MB
__device__ float g_h0[(size_t)NN * HID];    // 60 MB (fallback h0 storage)
__device__ int   g_cnt[NN];
__device__ int   g_rowptr[NN];
__device__ int   g_cursor[NN];
__device__ int   g_src_sorted[EE];
__device__ float g_w_sorted[EE];

// ---------------- kernel 1: zero inc + cnt ----------------
__global__ void zero_kernel(float* __restrict__ inc, int* __restrict__ cnt) {
    int idx = blockIdx.x * blockDim.x + threadIdx.x;
    int stride = gridDim.x * blockDim.x;
    for (int i = idx; i < NN * EDGE_D; i += stride) inc[i] = 0.f;
    for (int i = idx; i < NN; i += stride) cnt[i] = 0;
}

// ---------------- kernel 2: scatter edge features + histogram ----------------
// thread = e*16 + d  (coalesced read of edge_attr)
__global__ void edge_scatter_kernel(const float* __restrict__ edge_attr,
                                    const float* __restrict__ edge_weight,
                                    const int* __restrict__ edge_index,
                                    float* __restrict__ inc,
                                    int* __restrict__ cnt) {
    int tid = blockIdx.x * blockDim.x + threadIdx.x;
    if (tid >= EE * EDGE_D) return;
    int e = tid >> 4;
    int d = tid & 15;
    int dst = edge_index[EE + e];
    float w = edge_weight[e];
    atomicAdd(&inc[dst * EDGE_D + d], w * edge_attr[tid]);
    if (d == 0) atomicAdd(&cnt[dst], 1);
}

// ---------------- kernel 3: single-block exclusive scan ----------------
__global__ void scan_kernel(const int* __restrict__ cnt,
                            int* __restrict__ rowptr,
                            int* __restrict__ cursor) {
    __shared__ int part[1024];
    const int n = NN;
    int t = threadIdx.x;
    const int chunk = (n + 1023) / 1024;
    int beg = t * chunk;
    int end = beg + chunk;
    if (beg > n) beg = n;
    if (end > n) end = n;
    int s = 0;
    for (int i = beg; i < end; i++) s += cnt[i];
    part[t] = s;
    __syncthreads();
    // Hillis-Steele inclusive scan
    for (int off = 1; off < 1024; off <<= 1) {
        int v = (t >= off) ? part[t - off] : 0;
        __syncthreads();
        part[t] += v;
        __syncthreads();
    }
    int run = part[t] - s;   // exclusive prefix for this thread's chunk
    for (int i = beg; i < end; i++) {
        rowptr[i] = run;
        cursor[i] = run;
        run += cnt[i];
    }
}

// ---------------- kernel 4: bucket edges by dst ----------------
__global__ void fill_kernel(const float* __restrict__ edge_weight,
                            const int* __restrict__ edge_index,
                            int* __restrict__ cursor,
                            int* __restrict__ src_sorted,
                            float* __restrict__ w_sorted) {
    int e = blockIdx.x * blockDim.x + threadIdx.x;
    if (e >= EE) return;
    int src = edge_index[e];
    int dst = edge_index[EE + e];
    int pos = atomicAdd(&cursor[dst], 1);
    src_sorted[pos] = src;
    w_sorted[pos]   = edge_weight[e];
}

// ---------------- kernel 5/7: tiled GEMM + bias + optional resid + relu -------
// C[M,Nn] = relu( A @ B + bias (+ resid) ), A row-major [M,K], B row-major [K,Nn]
// CONCAT: A element (m,k) comes from A (k<K1, ld=K1) else A2 (ld=K-K1).
template<bool CONCAT, bool RESID>
__global__ __launch_bounds__(256)
void gemm_bias_relu(const float* __restrict__ A, const float* __restrict__ A2, int K1,
                    const float* __restrict__ B, const float* __restrict__ bias,
                    const float* __restrict__ resid,
                    float* __restrict__ C, int M, int Nn, int K) {
    const int BM = 64, BN = 64, BK = 16;
    __shared__ float As[BK][BM + 1];
    __shared__ float Bs[BK][BN];
    int tid = threadIdx.x;
    int tx = tid & 15;        // 0..15 -> col group
    int ty = tid >> 4;        // 0..15 -> row group
    int m0 = blockIdx.y * BM;
    int n0 = blockIdx.x * BN;
    float c[4][4];
#pragma unroll
    for (int i = 0; i < 4; i++)
#pragma unroll
        for (int j = 0; j < 4; j++) c[i][j] = 0.f;

    for (int k0 = 0; k0 < K; k0 += BK) {
        // load A tile (64 rows x 16 k), transposed into As[k][m]
#pragma unroll
        for (int it = 0; it < 4; it++) {
            int m = it * 16 + (tid >> 4);
            int k = tid & 15;
            int gm = m0 + m, gk = k0 + k;
            float v = 0.f;
            if (gm < M && gk < K) {
                if (CONCAT)
                    v = (gk < K1) ? A[(size_t)gm * K1 + gk]
                                  : A2[(size_t)gm * (K - K1) + (gk - K1)];
                else
                    v = A[(size_t)gm * K + gk];
            }
            As[k][m] = v;
        }
        // load B tile (16 k x 64 n)
#pragma unroll
        for (int it = 0; it < 4; it++) {
            int k = it * 4 + (tid >> 6);
            int nn = tid & 63;
            int gk = k0 + k, gn = n0 + nn;
            Bs[k][nn] = (gk < K && gn < Nn) ? B[(size_t)gk * Nn + gn] : 0.f;
        }
        __syncthreads();
#pragma unroll
        for (int kk = 0; kk < BK; kk++) {
            float a[4], bv[4];
#pragma unroll
            for (int i = 0; i < 4; i++) a[i] = As[kk][ty * 4 + i];
#pragma unroll
            for (int j = 0; j < 4; j++) bv[j] = Bs[kk][tx * 4 + j];
#pragma unroll
            for (int i = 0; i < 4; i++)
#pragma unroll
                for (int j = 0; j < 4; j++) c[i][j] += a[i] * bv[j];
        }
        __syncthreads();
    }
    // epilogue
#pragma unroll
    for (int i = 0; i < 4; i++) {
        int row = m0 + ty * 4 + i;
        if (row >= M) continue;
#pragma unroll
        for (int j = 0; j < 4; j++) {
            int col = n0 + tx * 4 + j;
            if (col >= Nn) continue;
            float v = c[i][j] + bias[col];
            if (RESID) v += resid[(size_t)row * Nn + col];
            v = fmaxf(v, 0.f);
            C[(size_t)row * Nn + col] = v;
        }
    }
}

// ---------------- kernel 6: per-node CSR aggregation (scatter-mean) -----------
__global__ __launch_bounds__(128)
void aggregate_kernel(const float* __restrict__ h0,
                      const int* __restrict__ rowptr,
                      const int* __restrict__ cnt_arr,
                      const int* __restrict__ src_sorted,
                      const float* __restrict__ w_sorted,
                      float* __restrict__ agg) {
    int i = blockIdx.x;
    int t = threadIdx.x;
    int start = rowptr[i];
    int cnt = cnt_arr[i];
    __shared__ int s_src[128];
    __shared__ float s_w[128];
    float acc0 = 0.f, acc1 = 0.f, acc2 = 0.f;
    for (int base = 0; base < cnt; base += 128) {
        int m = cnt - base; if (m > 128) m = 128;
        if (t < m) {
            s_src[t] = src_sorted[start + base + t];
            s_w[t]   = w_sorted[start + base + t];
        }
        __syncthreads();
        for (int j = 0; j < m; j++) {
            const float* row = h0 + (size_t)s_src[j] * HID;
            float w = s_w[j];
            acc0 += w * row[t];
            acc1 += w * row[t + 128];
            if (t + 256 < HID) acc2 += w * row[t + 256];
        }
        __syncthreads();
    }
    float inv = 1.0f / fmaxf((float)cnt, 1.0f);
    float* out = agg + (size_t)i * HID;
    out[t] = acc0 * inv;
    out[t + 128] = acc1 * inv;
    if (t + 256 < HID) out[t + 256] = acc2 * inv;
}

// ---------------- launch ----------------
extern "C" void kernel_launch(void* const* d_in, const int* in_sizes, int n_in,
                              void* d_out, int out_size) {
    // Bind inputs by unique element count (order-proof).
    const float* x = nullptr;           // 6,400,000
    const float* edge_attr = nullptr;   // 12,800,000
    const float* edge_weight = nullptr; // 800,000
    const float* W0 = nullptr;          // 43,200
    const float* b0 = nullptr;          // 300 (first)
    const float* W  = nullptr;          // 90,000
    const float* b  = nullptr;          // 300 (second)
    const int*   edge_index = nullptr;  // 1,600,000

    for (int i = 0; i < n_in; i++) {
        int s = in_sizes[i];
        switch (s) {
            case NN * NODE_D:      x = (const float*)d_in[i]; break;
            case EE * EDGE_D:      edge_attr = (const float*)d_in[i]; break;
            case EE:               edge_weight = (const float*)d_in[i]; break;
            case (NODE_D + EDGE_D) * HID: W0 = (const float*)d_in[i]; break;
            case HID * HID:        W = (const float*)d_in[i]; break;
            case 2 * EE:           edge_index = (const int*)d_in[i]; break;
            case HID:
                if (!b0) b0 = (const float*)d_in[i];
                else     b  = (const float*)d_in[i];
                break;
            default: break; // node_weight (50,000) unused
        }
    }
    if (!b) b = b0;

    // Resolve ALL device-symbol scratch addresses properly (host code must not
    // use __device__ symbols directly as pointers).
    void *p_inc, *p_agg, *p_h0, *p_cnt, *p_rowptr, *p_cursor, *p_src, *p_w;
    cudaGetSymbolAddress(&p_inc,    g_inc);
    cudaGetSymbolAddress(&p_agg,    g_agg);
    cudaGetSymbolAddress(&p_h0,     g_h0);
    cudaGetSymbolAddress(&p_cnt,    g_cnt);
    cudaGetSymbolAddress(&p_rowptr, g_rowptr);
    cudaGetSymbolAddress(&p_cursor, g_cursor);
    cudaGetSymbolAddress(&p_src,    g_src_sorted);
    cudaGetSymbolAddress(&p_w,      g_w_sorted);

    float* inc       = (float*)p_inc;
    float* agg       = (float*)p_agg;
    int*   cnt       = (int*)p_cnt;
    int*   rowptr    = (int*)p_rowptr;
    int*   cursor    = (int*)p_cursor;
    int*   src_sorted= (int*)p_src;
    float* w_sorted  = (float*)p_w;

    float* h = (float*)d_out;                           // [N,300], output 0
    // h0: into d_out second half if the harness holds both outputs, else scratch.
    float* h0 = (out_size >= 2 * NN * HID) ? (float*)d_out + (size_t)NN * HID
                                           : (float*)p_h0;

    // 1. zero scratch
    zero_kernel<<<2048, 256>>>(inc, cnt);

    // 2. scatter inc + histogram
    {
        int total = EE * EDGE_D;
        edge_scatter_kernel<<<(total + 255) / 256, 256>>>(edge_attr, edge_weight,
                                                          edge_index, inc, cnt);
    }

    // 3. scan -> rowptr/cursor
    scan_kernel<<<1, 1024>>>(cnt, rowptr, cursor);

    // 4. bucket edges
    fill_kernel<<<(EE + 255) / 256, 256>>>(edge_weight, edge_index,
                                           cursor, src_sorted, w_sorted);

    // 5. GEMM1: h0 = relu([x | inc] @ W0 + b0)
    {
        dim3 grid((HID + 63) / 64, (NN + 63) / 64);
        gemm_bias_relu<true, false><<<grid, 256>>>(x, inc, NODE_D,
                                                   W0, b0, nullptr,
                                                   h0, NN, HID, NODE_D + EDGE_D);
    }

    // 6. aggregation: agg = scatter_mean(edge_weight * h0[src], dst)
    aggregate_kernel<<<NN, 128>>>(h0, rowptr, cnt, src_sorted, w_sorted, agg);

    // 7. GEMM2: h = relu(h0 + agg @ W + b)
    {
        dim3 grid((HID + 63) / 64, (NN + 63) / 64);
        gemm_bias_relu<false, true><<<grid, 256>>>(agg, nullptr, 0,
                                                   W, b, h0,
                                                   h, NN, HID, HID);
    }
}